// round 12
// baseline (speedup 1.0000x reference)
#include <cuda_runtime.h>
#include <cstdint>

#define NMAX 200000
#define EMAX 6400000
#define CHUNK 2048
#define NCHUNKS ((NMAX + CHUNK - 1) / CHUNK)   // 98
#define GT 64   // gemm tile nodes

// Scratch (device globals — no allocation allowed)
__device__ int g_deg[NMAX];
__device__ int g_rowoff[NMAX];
__device__ int g_cursor[NMAX];
__device__ int g_csum[NCHUNKS];
__device__ int g_csr[EMAX];
__device__ __align__(16) float g_dinv[NMAX];
__device__ __align__(16) float g_tmpA[NMAX * 4];
__device__ __align__(16) float g_tmpB[NMAX * 4];
__device__ __align__(16) float g_tmpC[NMAX * 2];

static inline int cdiv(int a, int b) { return (a + b - 1) / b; }

// ============ merged K1: gemm role (4/5 of blocks) + count role (1/5) ============
__global__ void __launch_bounds__(128)
gemm_count_kernel(const float* __restrict__ x, const float* __restrict__ W,
                  const int* __restrict__ dst, int n, int e, int ntiles) {
    __shared__ float4 Wv[128];
    __shared__ float4 xs[GT * 33];
    __shared__ float4 ps[GT];

    int bid = blockIdx.x;
    int t = threadIdx.x;

    if ((bid % 5) == 4) {
        // ---- count role ----
        int cidx = bid / 5;
        int CB = gridDim.x / 5;
        int quads = e >> 2;
        for (int q = cidx * 128 + t; q < quads; q += CB * 128) {
            int4 d4 = __ldg((const int4*)dst + q);
            atomicAdd(&g_deg[d4.x], 1);
            atomicAdd(&g_deg[d4.y], 1);
            atomicAdd(&g_deg[d4.z], 1);
            atomicAdd(&g_deg[d4.w], 1);
        }
        if (cidx == 0 && t == 0)
            for (int i = quads * 4; i < e; i++) atomicAdd(&g_deg[dst[i]], 1);
        return;
    }

    // ---- gemm role ----
    int tile = bid - bid / 5;
    if (tile >= ntiles) return;
    if (t < 128) Wv[t] = ((const float4*)W)[t];
    int node0 = tile * GT;
    int nn = min(GT, n - node0);
    int tot = nn * 32;
    const float4* x4 = (const float4*)x;
    for (int idx = t; idx < tot; idx += 128) {
        int nd = idx >> 5, kq = idx & 31;
        xs[nd * 33 + kq] = x4[(size_t)(node0 + nd) * 32 + kq];
    }
    __syncthreads();
    int half = t >> 6;
    int node = t & 63;
    float4 acc = make_float4(0.f, 0.f, 0.f, 0.f);
    if (node < nn) {
        int k0 = half * 16;
        #pragma unroll
        for (int kq = 0; kq < 16; kq++) {
            float4 xv = xs[node * 33 + k0 + kq];
            float4 w0 = Wv[(k0 + kq) * 4 + 0];
            float4 w1 = Wv[(k0 + kq) * 4 + 1];
            float4 w2 = Wv[(k0 + kq) * 4 + 2];
            float4 w3 = Wv[(k0 + kq) * 4 + 3];
            acc.x += xv.x * w0.x + xv.y * w1.x + xv.z * w2.x + xv.w * w3.x;
            acc.y += xv.x * w0.y + xv.y * w1.y + xv.z * w2.y + xv.w * w3.y;
            acc.z += xv.x * w0.z + xv.y * w1.z + xv.z * w2.z + xv.w * w3.z;
            acc.w += xv.x * w0.w + xv.y * w1.w + xv.z * w2.w + xv.w * w3.w;
        }
    }
    if (half == 1) ps[node] = acc;
    __syncthreads();
    if (half == 0 && node < nn) {
        float4 b = ps[node];
        int i = node0 + node;
        *(float4*)(g_tmpA + (size_t)i * 4) =
            make_float4(acc.x + b.x, acc.y + b.y, acc.z + b.z, acc.w + b.w);
    }
}

// fallbacks (misaligned edge array)
__global__ void count_deg_scalar_kernel(const int* __restrict__ dst, int e) {
    int i = blockIdx.x * blockDim.x + threadIdx.x;
    if (i < e) atomicAdd(&g_deg[dst[i]], 1);
}
__global__ void gemm1_plain_kernel(const float* __restrict__ x, const float* __restrict__ W, int n) {
    __shared__ float4 Wv[128];
    __shared__ float4 xs[GT * 33];
    __shared__ float4 ps[GT];
    int t = threadIdx.x;
    if (t < 128) Wv[t] = ((const float4*)W)[t];
    int node0 = blockIdx.x * GT;
    int nn = min(GT, n - node0);
    int tot = nn * 32;
    const float4* x4 = (const float4*)x;
    for (int idx = t; idx < tot; idx += 128) {
        int nd = idx >> 5, kq = idx & 31;
        xs[nd * 33 + kq] = x4[(size_t)(node0 + nd) * 32 + kq];
    }
    __syncthreads();
    int half = t >> 6;
    int node = t & 63;
    float4 acc = make_float4(0.f, 0.f, 0.f, 0.f);
    if (node < nn) {
        int k0 = half * 16;
        #pragma unroll
        for (int kq = 0; kq < 16; kq++) {
            float4 xv = xs[node * 33 + k0 + kq];
            float4 w0 = Wv[(k0 + kq) * 4 + 0];
            float4 w1 = Wv[(k0 + kq) * 4 + 1];
            float4 w2 = Wv[(k0 + kq) * 4 + 2];
            float4 w3 = Wv[(k0 + kq) * 4 + 3];
            acc.x += xv.x * w0.x + xv.y * w1.x + xv.z * w2.x + xv.w * w3.x;
            acc.y += xv.x * w0.y + xv.y * w1.y + xv.z * w2.y + xv.w * w3.y;
            acc.z += xv.x * w0.z + xv.y * w1.z + xv.z * w2.z + xv.w * w3.z;
            acc.w += xv.x * w0.w + xv.y * w1.w + xv.z * w2.w + xv.w * w3.w;
        }
    }
    if (half == 1) ps[node] = acc;
    __syncthreads();
    if (half == 0 && node < nn) {
        float4 b = ps[node];
        int i = node0 + node;
        *(float4*)(g_tmpA + (size_t)i * 4) =
            make_float4(acc.x + b.x, acc.y + b.y, acc.z + b.z, acc.w + b.w);
    }
}

// ---------------- scanA: per-chunk exclusive scan (coalesced smem staging) ----------------
__global__ void scanA_kernel(int n) {
    __shared__ int sdeg[CHUNK];
    __shared__ int wsum[8], woff[8];
    int t = threadIdx.x;
    int c0 = blockIdx.x * CHUNK;
    #pragma unroll
    for (int r = 0; r < CHUNK / 256; r++) {
        int idx = t + r * 256;
        int node = c0 + idx;
        sdeg[idx] = (node < n) ? g_deg[node] : 0;
    }
    __syncthreads();
    int s = 0;
    #pragma unroll
    for (int r = 0; r < 8; r++) s += sdeg[t * 8 + r];
    int lane = t & 31, wid = t >> 5;
    int incl = s;
    #pragma unroll
    for (int off = 1; off < 32; off <<= 1) {
        int v = __shfl_up_sync(0xffffffffu, incl, off);
        if (lane >= off) incl += v;
    }
    if (lane == 31) wsum[wid] = incl;
    __syncthreads();
    if (t < 8) {
        int acc = 0;
        for (int w = 0; w < t; w++) acc += wsum[w];
        woff[t] = acc;
    }
    __syncthreads();
    int run = incl - s + woff[wid];
    #pragma unroll
    for (int r = 0; r < 8; r++) {
        int node = c0 + t * 8 + r;
        if (node < n) { g_rowoff[node] = run; run += sdeg[t * 8 + r]; }
    }
    if (t == 255) g_csum[blockIdx.x] = incl + woff[wid];
}

// scanC: warp-scan chunk offsets + apply + dinv + cursor + prescale tmpA
__global__ void scanC_kernel(int n, int nchunks) {
    __shared__ int coff[NCHUNKS + 32];
    int t = threadIdx.x;
    // cooperative prefix over <=98 chunk totals: warp 0 scans in 32-wide tiles
    if (t < 32) {
        int acc = 0;
        for (int b0 = 0; b0 < nchunks; b0 += 32) {
            int idx = b0 + t;
            int v = (idx < nchunks) ? g_csum[idx] : 0;
            int incl = v;
            #pragma unroll
            for (int off = 1; off < 32; off <<= 1) {
                int u = __shfl_up_sync(0xffffffffu, incl, off);
                if (t >= off) incl += u;
            }
            if (idx < nchunks) coff[idx] = acc + incl - v;
            int tot = __shfl_sync(0xffffffffu, incl, 31);
            acc += tot;
        }
    }
    __syncthreads();
    int i = blockIdx.x * blockDim.x + t;
    if (i >= n) return;
    int off = g_rowoff[i] + coff[i / CHUNK];
    g_rowoff[i] = off;
    g_cursor[i] = off;
    float dv = rsqrtf((float)(g_deg[i] + 1)); // +1 self-loop
    g_dinv[i] = dv;
    float4 v = *(const float4*)(g_tmpA + (size_t)i * 4);
    v.x *= dv; v.y *= dv; v.z *= dv; v.w *= dv;
    *(float4*)(g_tmpA + (size_t)i * 4) = v;
}

// ---------------- scatter: 16 edges/thread, atomics batched before stores ----------------
__global__ void __launch_bounds__(256)
scatter_kernel(const int* __restrict__ src, const int* __restrict__ dst, int e) {
    int t = blockIdx.x * blockDim.x + threadIdx.x;
    int base = t * 16;
    if (base >= e) return;
    if (base + 16 <= e) {
        int4 s0 = *(const int4*)(src + base);
        int4 s1 = *(const int4*)(src + base + 4);
        int4 s2 = *(const int4*)(src + base + 8);
        int4 s3 = *(const int4*)(src + base + 12);
        int4 d0 = *(const int4*)(dst + base);
        int4 d1 = *(const int4*)(dst + base + 4);
        int4 d2 = *(const int4*)(dst + base + 8);
        int4 d3 = *(const int4*)(dst + base + 12);
        // phase 1: all 16 independent atomics in flight
        int p0  = atomicAdd(&g_cursor[d0.x], 1);
        int p1  = atomicAdd(&g_cursor[d0.y], 1);
        int p2  = atomicAdd(&g_cursor[d0.z], 1);
        int p3  = atomicAdd(&g_cursor[d0.w], 1);
        int p4  = atomicAdd(&g_cursor[d1.x], 1);
        int p5  = atomicAdd(&g_cursor[d1.y], 1);
        int p6  = atomicAdd(&g_cursor[d1.z], 1);
        int p7  = atomicAdd(&g_cursor[d1.w], 1);
        int p8  = atomicAdd(&g_cursor[d2.x], 1);
        int p9  = atomicAdd(&g_cursor[d2.y], 1);
        int p10 = atomicAdd(&g_cursor[d2.z], 1);
        int p11 = atomicAdd(&g_cursor[d2.w], 1);
        int p12 = atomicAdd(&g_cursor[d3.x], 1);
        int p13 = atomicAdd(&g_cursor[d3.y], 1);
        int p14 = atomicAdd(&g_cursor[d3.z], 1);
        int p15 = atomicAdd(&g_cursor[d3.w], 1);
        // phase 2: stores
        g_csr[p0]  = s0.x; g_csr[p1]  = s0.y; g_csr[p2]  = s0.z; g_csr[p3]  = s0.w;
        g_csr[p4]  = s1.x; g_csr[p5]  = s1.y; g_csr[p6]  = s1.z; g_csr[p7]  = s1.w;
        g_csr[p8]  = s2.x; g_csr[p9]  = s2.y; g_csr[p10] = s2.z; g_csr[p11] = s2.w;
        g_csr[p12] = s3.x; g_csr[p13] = s3.y; g_csr[p14] = s3.z; g_csr[p15] = s3.w;
    } else {
        for (int i = base; i < e; i++) {
            int p = atomicAdd(&g_cursor[dst[i]], 1);
            g_csr[p] = src[i];
        }
    }
}
__global__ void scatter_scalar_kernel(const int* __restrict__ src, const int* __restrict__ dst, int e) {
    int i = blockIdx.x * blockDim.x + threadIdx.x;
    if (i >= e) return;
    int p = atomicAdd(&g_cursor[dst[i]], 1);
    g_csr[p] = src[i];
}

// ========= fused pull (FIN=4) =========
template <int FNEXT>
__global__ void __launch_bounds__(256, 6)
pull4_kernel(const float* __restrict__ tin,
             const float* __restrict__ b,
             const float* __restrict__ Wn,
             float* __restrict__ tout, int n) {
    int i = blockIdx.x * blockDim.x + threadIdx.x;
    if (i >= n) return;
    const float4* tp = (const float4*)tin;
    float4 a0 = tp[i];  // self-loop term (prescaled)
    float4 a1 = make_float4(0.f, 0.f, 0.f, 0.f), a2 = a1, a3 = a1;
    int j = g_rowoff[i];
    int jend = j + g_deg[i];
    for (; j + 4 <= jend; j += 4) {
        int s0 = __ldg(&g_csr[j]),     s1 = __ldg(&g_csr[j + 1]);
        int s2 = __ldg(&g_csr[j + 2]), s3 = __ldg(&g_csr[j + 3]);
        float4 v0 = tp[s0], v1 = tp[s1], v2 = tp[s2], v3 = tp[s3];
        a0.x += v0.x; a0.y += v0.y; a0.z += v0.z; a0.w += v0.w;
        a1.x += v1.x; a1.y += v1.y; a1.z += v1.z; a1.w += v1.w;
        a2.x += v2.x; a2.y += v2.y; a2.z += v2.z; a2.w += v2.w;
        a3.x += v3.x; a3.y += v3.y; a3.z += v3.z; a3.w += v3.w;
    }
    for (; j < jend; j++) {
        float4 v = tp[__ldg(&g_csr[j])];
        a0.x += v.x; a0.y += v.y; a0.z += v.z; a0.w += v.w;
    }
    float dv = g_dinv[i];
    float sx = (a0.x + a1.x) + (a2.x + a3.x);
    float sy = (a0.y + a1.y) + (a2.y + a3.y);
    float sz = (a0.z + a1.z) + (a2.z + a3.z);
    float sw = (a0.w + a1.w) + (a2.w + a3.w);
    float h0 = tanhf(sx * dv + __ldg(&b[0]));
    float h1 = tanhf(sy * dv + __ldg(&b[1]));
    float h2 = tanhf(sz * dv + __ldg(&b[2]));
    float h3 = tanhf(sw * dv + __ldg(&b[3]));
    if (FNEXT == 4) {
        float4 o;
        o.x = (h0*__ldg(&Wn[0*4+0]) + h1*__ldg(&Wn[1*4+0]) + h2*__ldg(&Wn[2*4+0]) + h3*__ldg(&Wn[3*4+0])) * dv;
        o.y = (h0*__ldg(&Wn[0*4+1]) + h1*__ldg(&Wn[1*4+1]) + h2*__ldg(&Wn[2*4+1]) + h3*__ldg(&Wn[3*4+1])) * dv;
        o.z = (h0*__ldg(&Wn[0*4+2]) + h1*__ldg(&Wn[1*4+2]) + h2*__ldg(&Wn[2*4+2]) + h3*__ldg(&Wn[3*4+2])) * dv;
        o.w = (h0*__ldg(&Wn[0*4+3]) + h1*__ldg(&Wn[1*4+3]) + h2*__ldg(&Wn[2*4+3]) + h3*__ldg(&Wn[3*4+3])) * dv;
        *(float4*)(tout + (size_t)i * 4) = o;
    } else {
        float2 o;
        o.x = (h0*__ldg(&Wn[0*2+0]) + h1*__ldg(&Wn[1*2+0]) + h2*__ldg(&Wn[2*2+0]) + h3*__ldg(&Wn[3*2+0])) * dv;
        o.y = (h0*__ldg(&Wn[0*2+1]) + h1*__ldg(&Wn[1*2+1]) + h2*__ldg(&Wn[2*2+1]) + h3*__ldg(&Wn[3*2+1])) * dv;
        *(float2*)(tout + (size_t)i * 2) = o;
    }
}

// ========= fused pull (FIN=2) + classifier + outputs =========
__global__ void __launch_bounds__(256, 6)
pull2_cls_kernel(const float* __restrict__ tin,
                 const float* __restrict__ b3,
                 const float* __restrict__ Wc,
                 const float* __restrict__ bc,
                 float* __restrict__ out,
                 float* __restrict__ hsec, int n) {
    int i = blockIdx.x * blockDim.x + threadIdx.x;
    if (i >= n) return;
    const float2* tp = (const float2*)tin;
    float2 a0 = tp[i];
    float2 a1 = make_float2(0.f, 0.f), a2 = a1, a3 = a1;
    int j = g_rowoff[i];
    int jend = j + g_deg[i];
    for (; j + 4 <= jend; j += 4) {
        int s0 = __ldg(&g_csr[j]),     s1 = __ldg(&g_csr[j + 1]);
        int s2 = __ldg(&g_csr[j + 2]), s3 = __ldg(&g_csr[j + 3]);
        float2 v0 = tp[s0], v1 = tp[s1], v2 = tp[s2], v3 = tp[s3];
        a0.x += v0.x; a0.y += v0.y;
        a1.x += v1.x; a1.y += v1.y;
        a2.x += v2.x; a2.y += v2.y;
        a3.x += v3.x; a3.y += v3.y;
    }
    for (; j < jend; j++) {
        float2 v = tp[__ldg(&g_csr[j])];
        a0.x += v.x; a0.y += v.y;
    }
    float dv = g_dinv[i];
    float sx = (a0.x + a1.x) + (a2.x + a3.x);
    float sy = (a0.y + a1.y) + (a2.y + a3.y);
    float h0 = tanhf(sx * dv + __ldg(&b3[0]));
    float h1 = tanhf(sy * dv + __ldg(&b3[1]));
    *(float2*)(hsec + (size_t)i * 2) = make_float2(h0, h1);
    #pragma unroll
    for (int j0 = 0; j0 < 16; j0 += 4) {
        float4 v;
        v.x = h0*__ldg(&Wc[0*16+j0+0]) + h1*__ldg(&Wc[1*16+j0+0]) + __ldg(&bc[j0+0]);
        v.y = h0*__ldg(&Wc[0*16+j0+1]) + h1*__ldg(&Wc[1*16+j0+1]) + __ldg(&bc[j0+1]);
        v.z = h0*__ldg(&Wc[0*16+j0+2]) + h1*__ldg(&Wc[1*16+j0+2]) + __ldg(&bc[j0+2]);
        v.w = h0*__ldg(&Wc[0*16+j0+3]) + h1*__ldg(&Wc[1*16+j0+3]) + __ldg(&bc[j0+3]);
        *(float4*)(out + (size_t)i * 16 + j0) = v;
    }
}

extern "C" void kernel_launch(void* const* d_in, const int* in_sizes, int n_in,
                              void* d_out, int out_size) {
    const float* x  = (const float*)d_in[0];
    const float* W1 = (const float*)d_in[1];
    const float* b1 = (const float*)d_in[2];
    const float* W2 = (const float*)d_in[3];
    const float* b2 = (const float*)d_in[4];
    const float* W3 = (const float*)d_in[5];
    const float* b3 = (const float*)d_in[6];
    const float* Wc = (const float*)d_in[7];
    const float* bc = (const float*)d_in[8];
    const int*   ei = (const int*)d_in[9];

    const int n = in_sizes[0] / 128;
    const int e = in_sizes[9] / 2;
    const int* src = ei;
    const int* dst = ei + e;

    const int B = 256;
    const bool vec = ((e & 3) == 0) &&
                     ((((unsigned long long)(uintptr_t)dst) & 15ull) == 0) &&
                     ((((unsigned long long)(uintptr_t)src) & 15ull) == 0);

    int*   deg_p;  cudaGetSymbolAddress((void**)&deg_p, g_deg);
    float* tmpA;   cudaGetSymbolAddress((void**)&tmpA, g_tmpA);
    float* tmpB;   cudaGetSymbolAddress((void**)&tmpB, g_tmpB);
    float* tmpC;   cudaGetSymbolAddress((void**)&tmpC, g_tmpC);

    cudaMemsetAsync(deg_p, 0, (size_t)n * sizeof(int));

    const int ntiles = cdiv(n, GT);
    if (vec) {
        int T = cdiv(ntiles * 5, 4);
        gemm_count_kernel<<<T, 128>>>(x, W1, dst, n, e, ntiles);
    } else {
        gemm1_plain_kernel<<<ntiles, 128>>>(x, W1, n);
        count_deg_scalar_kernel<<<cdiv(e, B), B>>>(dst, e);
    }

    scanA_kernel<<<cdiv(n, CHUNK), 256>>>(n);
    scanC_kernel<<<cdiv(n, B), B>>>(n, cdiv(n, CHUNK));  // also prescales tmpA
    if (vec) scatter_kernel<<<cdiv(cdiv(e, 16), B), B>>>(src, dst, e);
    else     scatter_scalar_kernel<<<cdiv(e, B), B>>>(src, dst, e);

    pull4_kernel<4><<<cdiv(n, B), B>>>(tmpA, b1, W2, tmpB, n);
    pull4_kernel<2><<<cdiv(n, B), B>>>(tmpB, b2, W3, tmpC, n);

    float* out  = (float*)d_out;
    float* hsec = out + (size_t)n * 16;
    pull2_cls_kernel<<<cdiv(n, B), B>>>(tmpC, b3, Wc, bc, out, hsec, n);
}

// round 13
// speedup vs baseline: 1.0243x; 1.0243x over previous
#include <cuda_runtime.h>
#include <cstdint>

#define NMAX 200000
#define EMAX 6400000
#define CHUNK 2048
#define NCHUNKS ((NMAX + CHUNK - 1) / CHUNK)   // 98
#define GT 64   // gemm tile nodes

// Scratch (device globals — no allocation allowed)
__device__ int g_deg[NMAX];
__device__ int g_rowoff[NMAX];
__device__ int g_cursor[NMAX];
__device__ int g_csum[NCHUNKS];
__device__ int g_csr[EMAX];
__device__ __align__(16) float g_dinv[NMAX];
__device__ __align__(16) float g_tmpA[NMAX * 4];
__device__ __align__(16) float g_tmpB[NMAX * 4];
__device__ __align__(16) float g_tmpC[NMAX * 2];

static inline int cdiv(int a, int b) { return (a + b - 1) / b; }

// ============ merged K1: gemm role (4/5 of blocks) + count role (1/5) ============
__global__ void __launch_bounds__(128)
gemm_count_kernel(const float* __restrict__ x, const float* __restrict__ W,
                  const int* __restrict__ dst, int n, int e, int ntiles) {
    __shared__ float4 Wv[128];
    __shared__ float4 xs[GT * 33];
    __shared__ float4 ps[GT];

    int bid = blockIdx.x;
    int t = threadIdx.x;

    if ((bid % 5) == 4) {
        // ---- count role ----
        int cidx = bid / 5;
        int CB = gridDim.x / 5;
        int quads = e >> 2;
        for (int q = cidx * 128 + t; q < quads; q += CB * 128) {
            int4 d4 = __ldg((const int4*)dst + q);
            atomicAdd(&g_deg[d4.x], 1);
            atomicAdd(&g_deg[d4.y], 1);
            atomicAdd(&g_deg[d4.z], 1);
            atomicAdd(&g_deg[d4.w], 1);
        }
        if (cidx == 0 && t == 0)
            for (int i = quads * 4; i < e; i++) atomicAdd(&g_deg[dst[i]], 1);
        return;
    }

    // ---- gemm role ----
    int tile = bid - bid / 5;
    if (tile >= ntiles) return;
    if (t < 128) Wv[t] = ((const float4*)W)[t];
    int node0 = tile * GT;
    int nn = min(GT, n - node0);
    int tot = nn * 32;
    const float4* x4 = (const float4*)x;
    for (int idx = t; idx < tot; idx += 128) {
        int nd = idx >> 5, kq = idx & 31;
        xs[nd * 33 + kq] = x4[(size_t)(node0 + nd) * 32 + kq];
    }
    __syncthreads();
    int half = t >> 6;
    int node = t & 63;
    float4 acc = make_float4(0.f, 0.f, 0.f, 0.f);
    if (node < nn) {
        int k0 = half * 16;
        #pragma unroll
        for (int kq = 0; kq < 16; kq++) {
            float4 xv = xs[node * 33 + k0 + kq];
            float4 w0 = Wv[(k0 + kq) * 4 + 0];
            float4 w1 = Wv[(k0 + kq) * 4 + 1];
            float4 w2 = Wv[(k0 + kq) * 4 + 2];
            float4 w3 = Wv[(k0 + kq) * 4 + 3];
            acc.x += xv.x * w0.x + xv.y * w1.x + xv.z * w2.x + xv.w * w3.x;
            acc.y += xv.x * w0.y + xv.y * w1.y + xv.z * w2.y + xv.w * w3.y;
            acc.z += xv.x * w0.z + xv.y * w1.z + xv.z * w2.z + xv.w * w3.z;
            acc.w += xv.x * w0.w + xv.y * w1.w + xv.z * w2.w + xv.w * w3.w;
        }
    }
    if (half == 1) ps[node] = acc;
    __syncthreads();
    if (half == 0 && node < nn) {
        float4 b = ps[node];
        int i = node0 + node;
        *(float4*)(g_tmpA + (size_t)i * 4) =
            make_float4(acc.x + b.x, acc.y + b.y, acc.z + b.z, acc.w + b.w);
    }
}

// fallbacks (misaligned edge array)
__global__ void count_deg_scalar_kernel(const int* __restrict__ dst, int e) {
    int i = blockIdx.x * blockDim.x + threadIdx.x;
    if (i < e) atomicAdd(&g_deg[dst[i]], 1);
}
__global__ void gemm1_plain_kernel(const float* __restrict__ x, const float* __restrict__ W, int n) {
    __shared__ float4 Wv[128];
    __shared__ float4 xs[GT * 33];
    __shared__ float4 ps[GT];
    int t = threadIdx.x;
    if (t < 128) Wv[t] = ((const float4*)W)[t];
    int node0 = blockIdx.x * GT;
    int nn = min(GT, n - node0);
    int tot = nn * 32;
    const float4* x4 = (const float4*)x;
    for (int idx = t; idx < tot; idx += 128) {
        int nd = idx >> 5, kq = idx & 31;
        xs[nd * 33 + kq] = x4[(size_t)(node0 + nd) * 32 + kq];
    }
    __syncthreads();
    int half = t >> 6;
    int node = t & 63;
    float4 acc = make_float4(0.f, 0.f, 0.f, 0.f);
    if (node < nn) {
        int k0 = half * 16;
        #pragma unroll
        for (int kq = 0; kq < 16; kq++) {
            float4 xv = xs[node * 33 + k0 + kq];
            float4 w0 = Wv[(k0 + kq) * 4 + 0];
            float4 w1 = Wv[(k0 + kq) * 4 + 1];
            float4 w2 = Wv[(k0 + kq) * 4 + 2];
            float4 w3 = Wv[(k0 + kq) * 4 + 3];
            acc.x += xv.x * w0.x + xv.y * w1.x + xv.z * w2.x + xv.w * w3.x;
            acc.y += xv.x * w0.y + xv.y * w1.y + xv.z * w2.y + xv.w * w3.y;
            acc.z += xv.x * w0.z + xv.y * w1.z + xv.z * w2.z + xv.w * w3.z;
            acc.w += xv.x * w0.w + xv.y * w1.w + xv.z * w2.w + xv.w * w3.w;
        }
    }
    if (half == 1) ps[node] = acc;
    __syncthreads();
    if (half == 0 && node < nn) {
        float4 b = ps[node];
        int i = node0 + node;
        *(float4*)(g_tmpA + (size_t)i * 4) =
            make_float4(acc.x + b.x, acc.y + b.y, acc.z + b.z, acc.w + b.w);
    }
}

// ---------------- scanA: per-chunk exclusive scan (coalesced smem staging) ----------------
__global__ void scanA_kernel(int n) {
    __shared__ int sdeg[CHUNK];
    __shared__ int wsum[8], woff[8];
    int t = threadIdx.x;
    int c0 = blockIdx.x * CHUNK;
    #pragma unroll
    for (int r = 0; r < CHUNK / 256; r++) {
        int idx = t + r * 256;
        int node = c0 + idx;
        sdeg[idx] = (node < n) ? g_deg[node] : 0;
    }
    __syncthreads();
    int s = 0;
    #pragma unroll
    for (int r = 0; r < 8; r++) s += sdeg[t * 8 + r];
    int lane = t & 31, wid = t >> 5;
    int incl = s;
    #pragma unroll
    for (int off = 1; off < 32; off <<= 1) {
        int v = __shfl_up_sync(0xffffffffu, incl, off);
        if (lane >= off) incl += v;
    }
    if (lane == 31) wsum[wid] = incl;
    __syncthreads();
    if (t < 8) {
        int acc = 0;
        for (int w = 0; w < t; w++) acc += wsum[w];
        woff[t] = acc;
    }
    __syncthreads();
    int run = incl - s + woff[wid];
    #pragma unroll
    for (int r = 0; r < 8; r++) {
        int node = c0 + t * 8 + r;
        if (node < n) { g_rowoff[node] = run; run += sdeg[t * 8 + r]; }
    }
    if (t == 255) g_csum[blockIdx.x] = incl + woff[wid];
}

// scanC: warp-scan chunk offsets + apply + dinv + cursor + prescale tmpA
__global__ void scanC_kernel(int n, int nchunks) {
    __shared__ int coff[NCHUNKS + 32];
    int t = threadIdx.x;
    if (t < 32) {
        int acc = 0;
        for (int b0 = 0; b0 < nchunks; b0 += 32) {
            int idx = b0 + t;
            int v = (idx < nchunks) ? g_csum[idx] : 0;
            int incl = v;
            #pragma unroll
            for (int off = 1; off < 32; off <<= 1) {
                int u = __shfl_up_sync(0xffffffffu, incl, off);
                if (t >= off) incl += u;
            }
            if (idx < nchunks) coff[idx] = acc + incl - v;
            int tot = __shfl_sync(0xffffffffu, incl, 31);
            acc += tot;
        }
    }
    __syncthreads();
    int i = blockIdx.x * blockDim.x + t;
    if (i >= n) return;
    int off = g_rowoff[i] + coff[i / CHUNK];
    g_rowoff[i] = off;
    g_cursor[i] = off;
    float dv = rsqrtf((float)(g_deg[i] + 1)); // +1 self-loop
    g_dinv[i] = dv;
    float4 v = *(const float4*)(g_tmpA + (size_t)i * 4);
    v.x *= dv; v.y *= dv; v.z *= dv; v.w *= dv;
    *(float4*)(g_tmpA + (size_t)i * 4) = v;
}

// ---------------- scatter: 4 edges/thread (R11 measured-best shape) ----------------
__global__ void scatter_kernel(const int* __restrict__ src, const int* __restrict__ dst, int e) {
    int t = blockIdx.x * blockDim.x + threadIdx.x;
    int base = t * 4;
    if (base >= e) return;
    if (base + 4 <= e) {
        int4 s4 = *(const int4*)(src + base);
        int4 d4 = *(const int4*)(dst + base);
        int p;
        p = atomicAdd(&g_cursor[d4.x], 1); g_csr[p] = s4.x;
        p = atomicAdd(&g_cursor[d4.y], 1); g_csr[p] = s4.y;
        p = atomicAdd(&g_cursor[d4.z], 1); g_csr[p] = s4.z;
        p = atomicAdd(&g_cursor[d4.w], 1); g_csr[p] = s4.w;
    } else {
        for (int i = base; i < e; i++) {
            int p = atomicAdd(&g_cursor[dst[i]], 1);
            g_csr[p] = src[i];
        }
    }
}
__global__ void scatter_scalar_kernel(const int* __restrict__ src, const int* __restrict__ dst, int e) {
    int i = blockIdx.x * blockDim.x + threadIdx.x;
    if (i >= e) return;
    int p = atomicAdd(&g_cursor[dst[i]], 1);
    g_csr[p] = src[i];
}

// ========= fused pull (FIN=4): unroll 8, high occupancy =========
template <int FNEXT>
__global__ void __launch_bounds__(256, 6)
pull4_kernel(const float* __restrict__ tin,
             const float* __restrict__ b,
             const float* __restrict__ Wn,
             float* __restrict__ tout, int n) {
    int i = blockIdx.x * blockDim.x + threadIdx.x;
    if (i >= n) return;
    const float4* tp = (const float4*)tin;
    float4 a0 = tp[i];  // self-loop term (prescaled)
    float4 a1 = make_float4(0.f, 0.f, 0.f, 0.f), a2 = a1, a3 = a1;
    int j = g_rowoff[i];
    int jend = j + g_deg[i];
    for (; j + 8 <= jend; j += 8) {
        int s0 = __ldg(&g_csr[j]),     s1 = __ldg(&g_csr[j + 1]);
        int s2 = __ldg(&g_csr[j + 2]), s3 = __ldg(&g_csr[j + 3]);
        int s4 = __ldg(&g_csr[j + 4]), s5 = __ldg(&g_csr[j + 5]);
        int s6 = __ldg(&g_csr[j + 6]), s7 = __ldg(&g_csr[j + 7]);
        float4 v0 = tp[s0], v1 = tp[s1], v2 = tp[s2], v3 = tp[s3];
        float4 v4 = tp[s4], v5 = tp[s5], v6 = tp[s6], v7 = tp[s7];
        a0.x += v0.x; a0.y += v0.y; a0.z += v0.z; a0.w += v0.w;
        a1.x += v1.x; a1.y += v1.y; a1.z += v1.z; a1.w += v1.w;
        a2.x += v2.x; a2.y += v2.y; a2.z += v2.z; a2.w += v2.w;
        a3.x += v3.x; a3.y += v3.y; a3.z += v3.z; a3.w += v3.w;
        a0.x += v4.x; a0.y += v4.y; a0.z += v4.z; a0.w += v4.w;
        a1.x += v5.x; a1.y += v5.y; a1.z += v5.z; a1.w += v5.w;
        a2.x += v6.x; a2.y += v6.y; a2.z += v6.z; a2.w += v6.w;
        a3.x += v7.x; a3.y += v7.y; a3.z += v7.z; a3.w += v7.w;
    }
    for (; j < jend; j++) {
        float4 v = tp[__ldg(&g_csr[j])];
        a0.x += v.x; a0.y += v.y; a0.z += v.z; a0.w += v.w;
    }
    float dv = g_dinv[i];
    float sx = (a0.x + a1.x) + (a2.x + a3.x);
    float sy = (a0.y + a1.y) + (a2.y + a3.y);
    float sz = (a0.z + a1.z) + (a2.z + a3.z);
    float sw = (a0.w + a1.w) + (a2.w + a3.w);
    float h0 = tanhf(sx * dv + __ldg(&b[0]));
    float h1 = tanhf(sy * dv + __ldg(&b[1]));
    float h2 = tanhf(sz * dv + __ldg(&b[2]));
    float h3 = tanhf(sw * dv + __ldg(&b[3]));
    if (FNEXT == 4) {
        float4 o;
        o.x = (h0*__ldg(&Wn[0*4+0]) + h1*__ldg(&Wn[1*4+0]) + h2*__ldg(&Wn[2*4+0]) + h3*__ldg(&Wn[3*4+0])) * dv;
        o.y = (h0*__ldg(&Wn[0*4+1]) + h1*__ldg(&Wn[1*4+1]) + h2*__ldg(&Wn[2*4+1]) + h3*__ldg(&Wn[3*4+1])) * dv;
        o.z = (h0*__ldg(&Wn[0*4+2]) + h1*__ldg(&Wn[1*4+2]) + h2*__ldg(&Wn[2*4+2]) + h3*__ldg(&Wn[3*4+2])) * dv;
        o.w = (h0*__ldg(&Wn[0*4+3]) + h1*__ldg(&Wn[1*4+3]) + h2*__ldg(&Wn[2*4+3]) + h3*__ldg(&Wn[3*4+3])) * dv;
        *(float4*)(tout + (size_t)i * 4) = o;
    } else {
        float2 o;
        o.x = (h0*__ldg(&Wn[0*2+0]) + h1*__ldg(&Wn[1*2+0]) + h2*__ldg(&Wn[2*2+0]) + h3*__ldg(&Wn[3*2+0])) * dv;
        o.y = (h0*__ldg(&Wn[0*2+1]) + h1*__ldg(&Wn[1*2+1]) + h2*__ldg(&Wn[2*2+1]) + h3*__ldg(&Wn[3*2+1])) * dv;
        *(float2*)(tout + (size_t)i * 2) = o;
    }
}

// ========= fused pull (FIN=2) + classifier + outputs =========
__global__ void __launch_bounds__(256, 6)
pull2_cls_kernel(const float* __restrict__ tin,
                 const float* __restrict__ b3,
                 const float* __restrict__ Wc,
                 const float* __restrict__ bc,
                 float* __restrict__ out,
                 float* __restrict__ hsec, int n) {
    int i = blockIdx.x * blockDim.x + threadIdx.x;
    if (i >= n) return;
    const float2* tp = (const float2*)tin;
    float2 a0 = tp[i];
    float2 a1 = make_float2(0.f, 0.f), a2 = a1, a3 = a1;
    int j = g_rowoff[i];
    int jend = j + g_deg[i];
    for (; j + 8 <= jend; j += 8) {
        int s0 = __ldg(&g_csr[j]),     s1 = __ldg(&g_csr[j + 1]);
        int s2 = __ldg(&g_csr[j + 2]), s3 = __ldg(&g_csr[j + 3]);
        int s4 = __ldg(&g_csr[j + 4]), s5 = __ldg(&g_csr[j + 5]);
        int s6 = __ldg(&g_csr[j + 6]), s7 = __ldg(&g_csr[j + 7]);
        float2 v0 = tp[s0], v1 = tp[s1], v2 = tp[s2], v3 = tp[s3];
        float2 v4 = tp[s4], v5 = tp[s5], v6 = tp[s6], v7 = tp[s7];
        a0.x += v0.x; a0.y += v0.y;
        a1.x += v1.x; a1.y += v1.y;
        a2.x += v2.x; a2.y += v2.y;
        a3.x += v3.x; a3.y += v3.y;
        a0.x += v4.x; a0.y += v4.y;
        a1.x += v5.x; a1.y += v5.y;
        a2.x += v6.x; a2.y += v6.y;
        a3.x += v7.x; a3.y += v7.y;
    }
    for (; j < jend; j++) {
        float2 v = tp[__ldg(&g_csr[j])];
        a0.x += v.x; a0.y += v.y;
    }
    float dv = g_dinv[i];
    float sx = (a0.x + a1.x) + (a2.x + a3.x);
    float sy = (a0.y + a1.y) + (a2.y + a3.y);
    float h0 = tanhf(sx * dv + __ldg(&b3[0]));
    float h1 = tanhf(sy * dv + __ldg(&b3[1]));
    *(float2*)(hsec + (size_t)i * 2) = make_float2(h0, h1);
    #pragma unroll
    for (int j0 = 0; j0 < 16; j0 += 4) {
        float4 v;
        v.x = h0*__ldg(&Wc[0*16+j0+0]) + h1*__ldg(&Wc[1*16+j0+0]) + __ldg(&bc[j0+0]);
        v.y = h0*__ldg(&Wc[0*16+j0+1]) + h1*__ldg(&Wc[1*16+j0+1]) + __ldg(&bc[j0+1]);
        v.z = h0*__ldg(&Wc[0*16+j0+2]) + h1*__ldg(&Wc[1*16+j0+2]) + __ldg(&bc[j0+2]);
        v.w = h0*__ldg(&Wc[0*16+j0+3]) + h1*__ldg(&Wc[1*16+j0+3]) + __ldg(&bc[j0+3]);
        *(float4*)(out + (size_t)i * 16 + j0) = v;
    }
}

extern "C" void kernel_launch(void* const* d_in, const int* in_sizes, int n_in,
                              void* d_out, int out_size) {
    const float* x  = (const float*)d_in[0];
    const float* W1 = (const float*)d_in[1];
    const float* b1 = (const float*)d_in[2];
    const float* W2 = (const float*)d_in[3];
    const float* b2 = (const float*)d_in[4];
    const float* W3 = (const float*)d_in[5];
    const float* b3 = (const float*)d_in[6];
    const float* Wc = (const float*)d_in[7];
    const float* bc = (const float*)d_in[8];
    const int*   ei = (const int*)d_in[9];

    const int n = in_sizes[0] / 128;
    const int e = in_sizes[9] / 2;
    const int* src = ei;
    const int* dst = ei + e;

    const int B = 256;
    const bool vec = ((e & 3) == 0) &&
                     ((((unsigned long long)(uintptr_t)dst) & 15ull) == 0) &&
                     ((((unsigned long long)(uintptr_t)src) & 15ull) == 0);

    int*   deg_p;  cudaGetSymbolAddress((void**)&deg_p, g_deg);
    float* tmpA;   cudaGetSymbolAddress((void**)&tmpA, g_tmpA);
    float* tmpB;   cudaGetSymbolAddress((void**)&tmpB, g_tmpB);
    float* tmpC;   cudaGetSymbolAddress((void**)&tmpC, g_tmpC);

    cudaMemsetAsync(deg_p, 0, (size_t)n * sizeof(int));

    const int ntiles = cdiv(n, GT);
    if (vec) {
        int T = cdiv(ntiles * 5, 4);
        gemm_count_kernel<<<T, 128>>>(x, W1, dst, n, e, ntiles);
    } else {
        gemm1_plain_kernel<<<ntiles, 128>>>(x, W1, n);
        count_deg_scalar_kernel<<<cdiv(e, B), B>>>(dst, e);
    }

    scanA_kernel<<<cdiv(n, CHUNK), 256>>>(n);
    scanC_kernel<<<cdiv(n, B), B>>>(n, cdiv(n, CHUNK));  // also prescales tmpA
    if (vec) scatter_kernel<<<cdiv(cdiv(e, 4), B), B>>>(src, dst, e);
    else     scatter_scalar_kernel<<<cdiv(e, B), B>>>(src, dst, e);

    pull4_kernel<4><<<cdiv(n, B), B>>>(tmpA, b1, W2, tmpB, n);
    pull4_kernel<2><<<cdiv(n, B), B>>>(tmpB, b2, W3, tmpC, n);

    float* out  = (float*)d_out;
    float* hsec = out + (size_t)n * 16;
    pull2_cls_kernel<<<cdiv(n, B), B>>>(tmpC, b3, Wc, bc, out, hsec, n);
}

// round 14
// speedup vs baseline: 1.0382x; 1.0135x over previous
#include <cuda_runtime.h>
#include <cstdint>

#define NMAX 200000
#define EMAX 6400000
#define CHUNK 2048
#define NCHUNKS ((NMAX + CHUNK - 1) / CHUNK)   // 98
#define GT 64   // gemm tile nodes

// Scratch (device globals — no allocation allowed)
__device__ int g_deg[NMAX];
__device__ int g_rowoff[NMAX];
__device__ int g_cursor[NMAX];
__device__ int g_csum[NCHUNKS];
__device__ int g_csr[EMAX];
__device__ __align__(16) float g_dinv[NMAX];
__device__ __align__(16) float g_tmpA[NMAX * 4];
__device__ __align__(16) float g_tmpB[NMAX * 4];
__device__ __align__(16) float g_tmpC[NMAX * 2];

static inline int cdiv(int a, int b) { return (a + b - 1) / b; }

// ============ merged K1: gemm role (3/5 of blocks) + count role (2/5) ============
__global__ void __launch_bounds__(128)
gemm_count_kernel(const float* __restrict__ x, const float* __restrict__ W,
                  const int* __restrict__ dst, int n, int e, int ntiles) {
    __shared__ float4 Wv[128];
    __shared__ float4 xs[GT * 33];
    __shared__ float4 ps[GT];

    int bid = blockIdx.x;
    int t = threadIdx.x;
    int r5 = bid % 5;

    if (r5 >= 3) {
        // ---- count role (2 of every 5 blocks) ----
        int cidx = (bid / 5) * 2 + (r5 - 3);
        int CB = (gridDim.x / 5) * 2;
        int quads = e >> 2;
        for (int q = cidx * 128 + t; q < quads; q += CB * 128) {
            int4 d4 = __ldg((const int4*)dst + q);
            atomicAdd(&g_deg[d4.x], 1);
            atomicAdd(&g_deg[d4.y], 1);
            atomicAdd(&g_deg[d4.z], 1);
            atomicAdd(&g_deg[d4.w], 1);
        }
        if (cidx == 0 && t == 0)
            for (int i = quads * 4; i < e; i++) atomicAdd(&g_deg[dst[i]], 1);
        return;
    }

    // ---- gemm role (3 of every 5 blocks) ----
    int tile = (bid / 5) * 3 + r5;
    if (tile >= ntiles) return;
    if (t < 128) Wv[t] = ((const float4*)W)[t];
    int node0 = tile * GT;
    int nn = min(GT, n - node0);
    int tot = nn * 32;
    const float4* x4 = (const float4*)x;
    for (int idx = t; idx < tot; idx += 128) {
        int nd = idx >> 5, kq = idx & 31;
        xs[nd * 33 + kq] = x4[(size_t)(node0 + nd) * 32 + kq];
    }
    __syncthreads();
    int half = t >> 6;
    int node = t & 63;
    float4 acc = make_float4(0.f, 0.f, 0.f, 0.f);
    if (node < nn) {
        int k0 = half * 16;
        #pragma unroll
        for (int kq = 0; kq < 16; kq++) {
            float4 xv = xs[node * 33 + k0 + kq];
            float4 w0 = Wv[(k0 + kq) * 4 + 0];
            float4 w1 = Wv[(k0 + kq) * 4 + 1];
            float4 w2 = Wv[(k0 + kq) * 4 + 2];
            float4 w3 = Wv[(k0 + kq) * 4 + 3];
            acc.x += xv.x * w0.x + xv.y * w1.x + xv.z * w2.x + xv.w * w3.x;
            acc.y += xv.x * w0.y + xv.y * w1.y + xv.z * w2.y + xv.w * w3.y;
            acc.z += xv.x * w0.z + xv.y * w1.z + xv.z * w2.z + xv.w * w3.z;
            acc.w += xv.x * w0.w + xv.y * w1.w + xv.z * w2.w + xv.w * w3.w;
        }
    }
    if (half == 1) ps[node] = acc;
    __syncthreads();
    if (half == 0 && node < nn) {
        float4 b = ps[node];
        int i = node0 + node;
        *(float4*)(g_tmpA + (size_t)i * 4) =
            make_float4(acc.x + b.x, acc.y + b.y, acc.z + b.z, acc.w + b.w);
    }
}

// fallbacks (misaligned edge array)
__global__ void count_deg_scalar_kernel(const int* __restrict__ dst, int e) {
    int i = blockIdx.x * blockDim.x + threadIdx.x;
    if (i < e) atomicAdd(&g_deg[dst[i]], 1);
}
__global__ void gemm1_plain_kernel(const float* __restrict__ x, const float* __restrict__ W, int n) {
    __shared__ float4 Wv[128];
    __shared__ float4 xs[GT * 33];
    __shared__ float4 ps[GT];
    int t = threadIdx.x;
    if (t < 128) Wv[t] = ((const float4*)W)[t];
    int node0 = blockIdx.x * GT;
    int nn = min(GT, n - node0);
    int tot = nn * 32;
    const float4* x4 = (const float4*)x;
    for (int idx = t; idx < tot; idx += 128) {
        int nd = idx >> 5, kq = idx & 31;
        xs[nd * 33 + kq] = x4[(size_t)(node0 + nd) * 32 + kq];
    }
    __syncthreads();
    int half = t >> 6;
    int node = t & 63;
    float4 acc = make_float4(0.f, 0.f, 0.f, 0.f);
    if (node < nn) {
        int k0 = half * 16;
        #pragma unroll
        for (int kq = 0; kq < 16; kq++) {
            float4 xv = xs[node * 33 + k0 + kq];
            float4 w0 = Wv[(k0 + kq) * 4 + 0];
            float4 w1 = Wv[(k0 + kq) * 4 + 1];
            float4 w2 = Wv[(k0 + kq) * 4 + 2];
            float4 w3 = Wv[(k0 + kq) * 4 + 3];
            acc.x += xv.x * w0.x + xv.y * w1.x + xv.z * w2.x + xv.w * w3.x;
            acc.y += xv.x * w0.y + xv.y * w1.y + xv.z * w2.y + xv.w * w3.y;
            acc.z += xv.x * w0.z + xv.y * w1.z + xv.z * w2.z + xv.w * w3.z;
            acc.w += xv.x * w0.w + xv.y * w1.w + xv.z * w2.w + xv.w * w3.w;
        }
    }
    if (half == 1) ps[node] = acc;
    __syncthreads();
    if (half == 0 && node < nn) {
        float4 b = ps[node];
        int i = node0 + node;
        *(float4*)(g_tmpA + (size_t)i * 4) =
            make_float4(acc.x + b.x, acc.y + b.y, acc.z + b.z, acc.w + b.w);
    }
}

// ---------------- scanA: per-chunk exclusive scan (coalesced smem staging) ----------------
__global__ void scanA_kernel(int n) {
    __shared__ int sdeg[CHUNK];
    __shared__ int wsum[8], woff[8];
    int t = threadIdx.x;
    int c0 = blockIdx.x * CHUNK;
    #pragma unroll
    for (int r = 0; r < CHUNK / 256; r++) {
        int idx = t + r * 256;
        int node = c0 + idx;
        sdeg[idx] = (node < n) ? g_deg[node] : 0;
    }
    __syncthreads();
    int s = 0;
    #pragma unroll
    for (int r = 0; r < 8; r++) s += sdeg[t * 8 + r];
    int lane = t & 31, wid = t >> 5;
    int incl = s;
    #pragma unroll
    for (int off = 1; off < 32; off <<= 1) {
        int v = __shfl_up_sync(0xffffffffu, incl, off);
        if (lane >= off) incl += v;
    }
    if (lane == 31) wsum[wid] = incl;
    __syncthreads();
    if (t < 8) {
        int acc = 0;
        for (int w = 0; w < t; w++) acc += wsum[w];
        woff[t] = acc;
    }
    __syncthreads();
    int run = incl - s + woff[wid];
    #pragma unroll
    for (int r = 0; r < 8; r++) {
        int node = c0 + t * 8 + r;
        if (node < n) { g_rowoff[node] = run; run += sdeg[t * 8 + r]; }
    }
    if (t == 255) g_csum[blockIdx.x] = incl + woff[wid];
}

// scanC: warp-scan chunk offsets + apply + dinv + cursor + prescale tmpA
__global__ void scanC_kernel(int n, int nchunks) {
    __shared__ int coff[NCHUNKS + 32];
    int t = threadIdx.x;
    if (t < 32) {
        int acc = 0;
        for (int b0 = 0; b0 < nchunks; b0 += 32) {
            int idx = b0 + t;
            int v = (idx < nchunks) ? g_csum[idx] : 0;
            int incl = v;
            #pragma unroll
            for (int off = 1; off < 32; off <<= 1) {
                int u = __shfl_up_sync(0xffffffffu, incl, off);
                if (t >= off) incl += u;
            }
            if (idx < nchunks) coff[idx] = acc + incl - v;
            int tot = __shfl_sync(0xffffffffu, incl, 31);
            acc += tot;
        }
    }
    __syncthreads();
    int i = blockIdx.x * blockDim.x + t;
    if (i >= n) return;
    int off = g_rowoff[i] + coff[i / CHUNK];
    g_rowoff[i] = off;
    g_cursor[i] = off;
    float dv = rsqrtf((float)(g_deg[i] + 1)); // +1 self-loop
    g_dinv[i] = dv;
    float4 v = *(const float4*)(g_tmpA + (size_t)i * 4);
    v.x *= dv; v.y *= dv; v.z *= dv; v.w *= dv;
    *(float4*)(g_tmpA + (size_t)i * 4) = v;
}

// ---------------- scatter: 4 edges/thread (measured-best shape) ----------------
__global__ void scatter_kernel(const int* __restrict__ src, const int* __restrict__ dst, int e) {
    int t = blockIdx.x * blockDim.x + threadIdx.x;
    int base = t * 4;
    if (base >= e) return;
    if (base + 4 <= e) {
        int4 s4 = *(const int4*)(src + base);
        int4 d4 = *(const int4*)(dst + base);
        int p;
        p = atomicAdd(&g_cursor[d4.x], 1); g_csr[p] = s4.x;
        p = atomicAdd(&g_cursor[d4.y], 1); g_csr[p] = s4.y;
        p = atomicAdd(&g_cursor[d4.z], 1); g_csr[p] = s4.z;
        p = atomicAdd(&g_cursor[d4.w], 1); g_csr[p] = s4.w;
    } else {
        for (int i = base; i < e; i++) {
            int p = atomicAdd(&g_cursor[dst[i]], 1);
            g_csr[p] = src[i];
        }
    }
}
__global__ void scatter_scalar_kernel(const int* __restrict__ src, const int* __restrict__ dst, int e) {
    int i = blockIdx.x * blockDim.x + threadIdx.x;
    if (i >= e) return;
    int p = atomicAdd(&g_cursor[dst[i]], 1);
    g_csr[p] = src[i];
}

// ========= fused pull (FIN=4): unroll 8, high occupancy =========
template <int FNEXT>
__global__ void __launch_bounds__(256, 6)
pull4_kernel(const float* __restrict__ tin,
             const float* __restrict__ b,
             const float* __restrict__ Wn,
             float* __restrict__ tout, int n) {
    int i = blockIdx.x * blockDim.x + threadIdx.x;
    if (i >= n) return;
    const float4* tp = (const float4*)tin;
    float4 a0 = tp[i];  // self-loop term (prescaled)
    float4 a1 = make_float4(0.f, 0.f, 0.f, 0.f), a2 = a1, a3 = a1;
    int j = g_rowoff[i];
    int jend = j + g_deg[i];
    for (; j + 8 <= jend; j += 8) {
        int s0 = __ldg(&g_csr[j]),     s1 = __ldg(&g_csr[j + 1]);
        int s2 = __ldg(&g_csr[j + 2]), s3 = __ldg(&g_csr[j + 3]);
        int s4 = __ldg(&g_csr[j + 4]), s5 = __ldg(&g_csr[j + 5]);
        int s6 = __ldg(&g_csr[j + 6]), s7 = __ldg(&g_csr[j + 7]);
        float4 v0 = tp[s0], v1 = tp[s1], v2 = tp[s2], v3 = tp[s3];
        float4 v4 = tp[s4], v5 = tp[s5], v6 = tp[s6], v7 = tp[s7];
        a0.x += v0.x; a0.y += v0.y; a0.z += v0.z; a0.w += v0.w;
        a1.x += v1.x; a1.y += v1.y; a1.z += v1.z; a1.w += v1.w;
        a2.x += v2.x; a2.y += v2.y; a2.z += v2.z; a2.w += v2.w;
        a3.x += v3.x; a3.y += v3.y; a3.z += v3.z; a3.w += v3.w;
        a0.x += v4.x; a0.y += v4.y; a0.z += v4.z; a0.w += v4.w;
        a1.x += v5.x; a1.y += v5.y; a1.z += v5.z; a1.w += v5.w;
        a2.x += v6.x; a2.y += v6.y; a2.z += v6.z; a2.w += v6.w;
        a3.x += v7.x; a3.y += v7.y; a3.z += v7.z; a3.w += v7.w;
    }
    for (; j < jend; j++) {
        float4 v = tp[__ldg(&g_csr[j])];
        a0.x += v.x; a0.y += v.y; a0.z += v.z; a0.w += v.w;
    }
    float dv = g_dinv[i];
    float sx = (a0.x + a1.x) + (a2.x + a3.x);
    float sy = (a0.y + a1.y) + (a2.y + a3.y);
    float sz = (a0.z + a1.z) + (a2.z + a3.z);
    float sw = (a0.w + a1.w) + (a2.w + a3.w);
    float h0 = tanhf(sx * dv + __ldg(&b[0]));
    float h1 = tanhf(sy * dv + __ldg(&b[1]));
    float h2 = tanhf(sz * dv + __ldg(&b[2]));
    float h3 = tanhf(sw * dv + __ldg(&b[3]));
    if (FNEXT == 4) {
        float4 o;
        o.x = (h0*__ldg(&Wn[0*4+0]) + h1*__ldg(&Wn[1*4+0]) + h2*__ldg(&Wn[2*4+0]) + h3*__ldg(&Wn[3*4+0])) * dv;
        o.y = (h0*__ldg(&Wn[0*4+1]) + h1*__ldg(&Wn[1*4+1]) + h2*__ldg(&Wn[2*4+1]) + h3*__ldg(&Wn[3*4+1])) * dv;
        o.z = (h0*__ldg(&Wn[0*4+2]) + h1*__ldg(&Wn[1*4+2]) + h2*__ldg(&Wn[2*4+2]) + h3*__ldg(&Wn[3*4+2])) * dv;
        o.w = (h0*__ldg(&Wn[0*4+3]) + h1*__ldg(&Wn[1*4+3]) + h2*__ldg(&Wn[2*4+3]) + h3*__ldg(&Wn[3*4+3])) * dv;
        *(float4*)(tout + (size_t)i * 4) = o;
    } else {
        float2 o;
        o.x = (h0*__ldg(&Wn[0*2+0]) + h1*__ldg(&Wn[1*2+0]) + h2*__ldg(&Wn[2*2+0]) + h3*__ldg(&Wn[3*2+0])) * dv;
        o.y = (h0*__ldg(&Wn[0*2+1]) + h1*__ldg(&Wn[1*2+1]) + h2*__ldg(&Wn[2*2+1]) + h3*__ldg(&Wn[3*2+1])) * dv;
        *(float2*)(tout + (size_t)i * 2) = o;
    }
}

// ========= fused pull (FIN=2) + classifier + outputs =========
__global__ void __launch_bounds__(256, 6)
pull2_cls_kernel(const float* __restrict__ tin,
                 const float* __restrict__ b3,
                 const float* __restrict__ Wc,
                 const float* __restrict__ bc,
                 float* __restrict__ out,
                 float* __restrict__ hsec, int n) {
    int i = blockIdx.x * blockDim.x + threadIdx.x;
    if (i >= n) return;
    const float2* tp = (const float2*)tin;
    float2 a0 = tp[i];
    float2 a1 = make_float2(0.f, 0.f), a2 = a1, a3 = a1;
    int j = g_rowoff[i];
    int jend = j + g_deg[i];
    for (; j + 8 <= jend; j += 8) {
        int s0 = __ldg(&g_csr[j]),     s1 = __ldg(&g_csr[j + 1]);
        int s2 = __ldg(&g_csr[j + 2]), s3 = __ldg(&g_csr[j + 3]);
        int s4 = __ldg(&g_csr[j + 4]), s5 = __ldg(&g_csr[j + 5]);
        int s6 = __ldg(&g_csr[j + 6]), s7 = __ldg(&g_csr[j + 7]);
        float2 v0 = tp[s0], v1 = tp[s1], v2 = tp[s2], v3 = tp[s3];
        float2 v4 = tp[s4], v5 = tp[s5], v6 = tp[s6], v7 = tp[s7];
        a0.x += v0.x; a0.y += v0.y;
        a1.x += v1.x; a1.y += v1.y;
        a2.x += v2.x; a2.y += v2.y;
        a3.x += v3.x; a3.y += v3.y;
        a0.x += v4.x; a0.y += v4.y;
        a1.x += v5.x; a1.y += v5.y;
        a2.x += v6.x; a2.y += v6.y;
        a3.x += v7.x; a3.y += v7.y;
    }
    for (; j < jend; j++) {
        float2 v = tp[__ldg(&g_csr[j])];
        a0.x += v.x; a0.y += v.y;
    }
    float dv = g_dinv[i];
    float sx = (a0.x + a1.x) + (a2.x + a3.x);
    float sy = (a0.y + a1.y) + (a2.y + a3.y);
    float h0 = tanhf(sx * dv + __ldg(&b3[0]));
    float h1 = tanhf(sy * dv + __ldg(&b3[1]));
    *(float2*)(hsec + (size_t)i * 2) = make_float2(h0, h1);
    #pragma unroll
    for (int j0 = 0; j0 < 16; j0 += 4) {
        float4 v;
        v.x = h0*__ldg(&Wc[0*16+j0+0]) + h1*__ldg(&Wc[1*16+j0+0]) + __ldg(&bc[j0+0]);
        v.y = h0*__ldg(&Wc[0*16+j0+1]) + h1*__ldg(&Wc[1*16+j0+1]) + __ldg(&bc[j0+1]);
        v.z = h0*__ldg(&Wc[0*16+j0+2]) + h1*__ldg(&Wc[1*16+j0+2]) + __ldg(&bc[j0+2]);
        v.w = h0*__ldg(&Wc[0*16+j0+3]) + h1*__ldg(&Wc[1*16+j0+3]) + __ldg(&bc[j0+3]);
        *(float4*)(out + (size_t)i * 16 + j0) = v;
    }
}

extern "C" void kernel_launch(void* const* d_in, const int* in_sizes, int n_in,
                              void* d_out, int out_size) {
    const float* x  = (const float*)d_in[0];
    const float* W1 = (const float*)d_in[1];
    const float* b1 = (const float*)d_in[2];
    const float* W2 = (const float*)d_in[3];
    const float* b2 = (const float*)d_in[4];
    const float* W3 = (const float*)d_in[5];
    const float* b3 = (const float*)d_in[6];
    const float* Wc = (const float*)d_in[7];
    const float* bc = (const float*)d_in[8];
    const int*   ei = (const int*)d_in[9];

    const int n = in_sizes[0] / 128;
    const int e = in_sizes[9] / 2;
    const int* src = ei;
    const int* dst = ei + e;

    const int B = 256;
    const bool vec = ((e & 3) == 0) &&
                     ((((unsigned long long)(uintptr_t)dst) & 15ull) == 0) &&
                     ((((unsigned long long)(uintptr_t)src) & 15ull) == 0);

    int*   deg_p;  cudaGetSymbolAddress((void**)&deg_p, g_deg);
    float* tmpA;   cudaGetSymbolAddress((void**)&tmpA, g_tmpA);
    float* tmpB;   cudaGetSymbolAddress((void**)&tmpB, g_tmpB);
    float* tmpC;   cudaGetSymbolAddress((void**)&tmpC, g_tmpC);

    cudaMemsetAsync(deg_p, 0, (size_t)n * sizeof(int));

    const int ntiles = cdiv(n, GT);
    if (vec) {
        int T = cdiv(ntiles, 3) * 5;   // 3 gemm : 2 count per 5 blocks
        gemm_count_kernel<<<T, 128>>>(x, W1, dst, n, e, ntiles);
    } else {
        gemm1_plain_kernel<<<ntiles, 128>>>(x, W1, n);
        count_deg_scalar_kernel<<<cdiv(e, B), B>>>(dst, e);
    }

    scanA_kernel<<<cdiv(n, CHUNK), 256>>>(n);
    scanC_kernel<<<cdiv(n, B), B>>>(n, cdiv(n, CHUNK));  // also prescales tmpA
    if (vec) scatter_kernel<<<cdiv(cdiv(e, 4), B), B>>>(src, dst, e);
    else     scatter_scalar_kernel<<<cdiv(e, B), B>>>(src, dst, e);

    pull4_kernel<4><<<cdiv(n, B), B>>>(tmpA, b1, W2, tmpB, n);
    pull4_kernel<2><<<cdiv(n, B), B>>>(tmpB, b2, W3, tmpC, n);

    float* out  = (float*)d_out;
    float* hsec = out + (size_t)n * 16;
    pull2_cls_kernel<<<cdiv(n, B), B>>>(tmpC, b3, Wc, bc, out, hsec, n);
}